// round 3
// baseline (speedup 1.0000x reference)
#include <cuda_runtime.h>
#include <cuda_bf16.h>
#include <math.h>

// ---------------------------------------------------------------------------
// B=1, N=2048, D=512, H=8, HD=64, NUM_OFFSETS=47
// ---------------------------------------------------------------------------
#define SEQ_N 2048
#define DIM_D 512
#define NHEAD 8
#define HDIM 64
#define NOFF 47

__constant__ int c_off[NOFF] = {
    0,1,2,3,4,5,6,7,8,9,10,11,12,13,14,15,16,17,18,19,20,21,22,23,24,25,26,
    27,28,29,30,31,32,48,64,96,128,192,256,384,512,768,1024,1536,2048,3072,4096
};

// Scratch: __device__ globals (cudaMalloc is forbidden).
__device__ float g_qkv [SEQ_N * 3 * DIM_D];  // 12 MB
__device__ float g_aout[SEQ_N * DIM_D];      // 4 MB
__device__ float g_gate[SEQ_N * DIM_D];      // 4 MB

// ---------------------------------------------------------------------------
// Shared SGEMM body: C[M,N] = A[M,K] @ B[K,N] (+bias), BM=64,BN=64,BK=16,
// 128 threads, 8x4 per thread. EPI: 0 = +bias, 1 = g_aout*sigmoid(acc+bias).
// ---------------------------------------------------------------------------
#define BM 64
#define BN 64
#define BK 16

__device__ __forceinline__ void sgemm_body(
    const float* __restrict__ A, const float* __restrict__ B,
    const float* __restrict__ bias, float* __restrict__ C,
    int M, int N, int K, int epi)
{
    __shared__ float As[BK][BM];
    __shared__ float Bs[BK][BN];

    const int tid = threadIdx.x;
    const int tx  = tid & 15;
    const int ty  = tid >> 4;
    const int brow = blockIdx.y * BM;
    const int bcol = blockIdx.x * BN;

    const int a_r = tid >> 2;
    const int a_c = (tid & 3) << 2;
    const int b_r = tid >> 4;
    const int b_c = (tid & 15) << 2;

    const float* Ap = A + (size_t)brow * K;
    const float* Bp = B + bcol;

    float acc[8][4];
    #pragma unroll
    for (int i = 0; i < 8; i++)
        #pragma unroll
        for (int j = 0; j < 4; j++) acc[i][j] = 0.f;

    for (int k0 = 0; k0 < K; k0 += BK) {
        float4 av0 = *(const float4*)(Ap + (size_t)(a_r     ) * K + k0 + a_c);
        float4 av1 = *(const float4*)(Ap + (size_t)(a_r + 32) * K + k0 + a_c);
        float4 bv0 = *(const float4*)(Bp + (size_t)(k0 + b_r    ) * N + b_c);
        float4 bv1 = *(const float4*)(Bp + (size_t)(k0 + b_r + 8) * N + b_c);

        As[a_c + 0][a_r] = av0.x; As[a_c + 1][a_r] = av0.y;
        As[a_c + 2][a_r] = av0.z; As[a_c + 3][a_r] = av0.w;
        As[a_c + 0][a_r + 32] = av1.x; As[a_c + 1][a_r + 32] = av1.y;
        As[a_c + 2][a_r + 32] = av1.z; As[a_c + 3][a_r + 32] = av1.w;
        *(float4*)&Bs[b_r    ][b_c] = bv0;
        *(float4*)&Bs[b_r + 8][b_c] = bv1;
        __syncthreads();

        #pragma unroll
        for (int kk = 0; kk < BK; kk++) {
            float4 a0 = *(const float4*)&As[kk][ty * 8];
            float4 a1 = *(const float4*)&As[kk][ty * 8 + 4];
            float4 bb = *(const float4*)&Bs[kk][tx * 4];
            float a[8] = {a0.x, a0.y, a0.z, a0.w, a1.x, a1.y, a1.z, a1.w};
            float b[4] = {bb.x, bb.y, bb.z, bb.w};
            #pragma unroll
            for (int i = 0; i < 8; i++)
                #pragma unroll
                for (int j = 0; j < 4; j++)
                    acc[i][j] = fmaf(a[i], b[j], acc[i][j]);
        }
        __syncthreads();
    }

    const int col = bcol + tx * 4;
    float4 bv = *(const float4*)(bias + col);
    #pragma unroll
    for (int i = 0; i < 8; i++) {
        const int row = brow + ty * 8 + i;
        float4 v;
        v.x = acc[i][0] + bv.x;
        v.y = acc[i][1] + bv.y;
        v.z = acc[i][2] + bv.z;
        v.w = acc[i][3] + bv.w;
        if (epi == 1) {
            float4 ax = *(const float4*)((const float*)g_aout + (size_t)row * N + col);
            v.x = ax.x / (1.f + __expf(-v.x));
            v.y = ax.y / (1.f + __expf(-v.y));
            v.z = ax.z / (1.f + __expf(-v.z));
            v.w = ax.w / (1.f + __expf(-v.w));
        }
        *(float4*)(C + (size_t)row * N + col) = v;
    }
}

__global__ void __launch_bounds__(128) gemm_qkv_kernel(
    const float* __restrict__ x, const float* __restrict__ W,
    const float* __restrict__ b)
{
    sgemm_body(x, W, b, (float*)g_qkv, SEQ_N, 3 * DIM_D, DIM_D, 0);
}

__global__ void __launch_bounds__(128) gemm_gate_kernel(
    const float* __restrict__ x, const float* __restrict__ W,
    const float* __restrict__ b)
{
    sgemm_body(x, W, b, (float*)g_gate, SEQ_N, DIM_D, DIM_D, 1);
}

__global__ void __launch_bounds__(128) gemm_out_kernel(
    const float* __restrict__ W, const float* __restrict__ b,
    float* __restrict__ out)
{
    sgemm_body((const float*)g_gate, W, b, out, SEQ_N, DIM_D, DIM_D, 0);
}

// ---------------------------------------------------------------------------
// Attention: one warp per (token n, head h). Reads g_qkv, writes g_aout.
// ---------------------------------------------------------------------------
__global__ void __launch_bounds__(256) attn_kernel(
    const float* __restrict__ pos_bias,    // [47,8]
    const float* __restrict__ scale_embed, // [47,64]
    const float* __restrict__ if_gain,     // [8]
    const float* __restrict__ disp_amp)    // [8]
{
    const float* qkv = (const float*)g_qkv;
    const int warp = threadIdx.x >> 5;
    const int lane = threadIdx.x & 31;
    const int n = blockIdx.x * 8 + warp;
    const int h = blockIdx.y;
    const int d0 = lane * 2;

    const float* qrow = qkv + (size_t)n * (3 * DIM_D) + h * HDIM;
    float2 q = *(const float2*)(qrow + d0);
    q.x *= 0.125f;  // 1/sqrt(64)
    q.y *= 0.125f;

    const float LM    = logf(4097.0f);
    const float wbase = 3.14159265358979f / LM;
    const float om = (h < 2) ? 0.f : (h < 4) ? wbase : (h < 6) ? 4.f * wbase : 6.f * wbase;
    const float da = disp_amp[h];

    float eb0, eb1 = 0.f;
    {
        const int o = lane;
        float ck = (om > 0.f) ? cosf(om * logf(1.f + (float)c_off[o])) : 0.f;
        eb0 = pos_bias[o * NHEAD + h] + ck * da;
        const int o2 = lane + 32;
        if (o2 < NOFF) {
            float ck2 = (om > 0.f) ? cosf(om * logf(1.f + (float)c_off[o2])) : 0.f;
            eb1 = pos_bias[o2 * NHEAD + h] + ck2 * da;
        }
    }

    float s0 = -INFINITY, s1 = -INFINITY;

    for (int o = 0; o < NOFF; o++) {
        const int j = n - c_off[o];
        if (j < 0) break;  // offsets ascending; warp-uniform break
        const float* krow = qkv + (size_t)j * (3 * DIM_D) + DIM_D + h * HDIM;
        float2 kv = *(const float2*)(krow + d0);
        float2 se = *(const float2*)(scale_embed + o * HDIM + d0);
        float p = q.x * kv.x * (1.f + se.x) + q.y * kv.y * (1.f + se.y);
        p += __shfl_xor_sync(0xffffffffu, p, 16);
        p += __shfl_xor_sync(0xffffffffu, p, 8);
        p += __shfl_xor_sync(0xffffffffu, p, 4);
        p += __shfl_xor_sync(0xffffffffu, p, 2);
        p += __shfl_xor_sync(0xffffffffu, p, 1);
        if (o < 32) { if (lane == o)      s0 = p + eb0; }
        else        { if (lane == o - 32) s1 = p + eb1; }
    }

    float m = fmaxf(s0, s1);
    m = fmaxf(m, __shfl_xor_sync(0xffffffffu, m, 16));
    m = fmaxf(m, __shfl_xor_sync(0xffffffffu, m, 8));
    m = fmaxf(m, __shfl_xor_sync(0xffffffffu, m, 4));
    m = fmaxf(m, __shfl_xor_sync(0xffffffffu, m, 2));
    m = fmaxf(m, __shfl_xor_sync(0xffffffffu, m, 1));

    float e0 = __expf(s0 - m);   // exp(-inf)=0
    float e1 = __expf(s1 - m);
    float z = e0 + e1;
    z += __shfl_xor_sync(0xffffffffu, z, 16);
    z += __shfl_xor_sync(0xffffffffu, z, 8);
    z += __shfl_xor_sync(0xffffffffu, z, 4);
    z += __shfl_xor_sync(0xffffffffu, z, 2);
    z += __shfl_xor_sync(0xffffffffu, z, 1);
    const float inv = 1.f / z;
    const float p0 = e0 * inv;
    const float p1 = e1 * inv;

    float2 acc = {0.f, 0.f};
    for (int o = 0; o < NOFF; o++) {
        const int j = n - c_off[o];
        if (j < 0) break;
        const float w = __shfl_sync(0xffffffffu, (o < 32) ? p0 : p1, o & 31);
        const float* vrow = qkv + (size_t)j * (3 * DIM_D) + 2 * DIM_D + h * HDIM;
        float2 vv = *(const float2*)(vrow + d0);
        acc.x = fmaf(w, vv.x, acc.x);
        acc.y = fmaf(w, vv.y, acc.y);
    }

    const float g = if_gain[h];
    float* aout = (float*)g_aout;
    float2 outv = {acc.x * g, acc.y * g};
    *(float2*)(aout + (size_t)n * DIM_D + h * HDIM + d0) = outv;
}

// ---------------------------------------------------------------------------
// Launch. Inputs: x, W_qkv, b_qkv, W_out, b_out, W_gate, b_gate, pos_bias,
// scale_embed, if_gain, disp_amp. Output: f32 [1,2048,512].
// ---------------------------------------------------------------------------
extern "C" void kernel_launch(void* const* d_in, const int* in_sizes, int n_in,
                              void* d_out, int out_size)
{
    const float* x        = (const float*)d_in[0];
    const float* W_qkv    = (const float*)d_in[1];
    const float* b_qkv    = (const float*)d_in[2];
    const float* W_out    = (const float*)d_in[3];
    const float* b_out    = (const float*)d_in[4];
    const float* W_gate   = (const float*)d_in[5];
    const float* b_gate   = (const float*)d_in[6];
    const float* pos_bias = (const float*)d_in[7];
    const float* scale_e  = (const float*)d_in[8];
    const float* if_gain  = (const float*)d_in[9];
    const float* disp_amp = (const float*)d_in[10];
    float* out = (float*)d_out;

    dim3 gq((3 * DIM_D) / BN, SEQ_N / BM);
    gemm_qkv_kernel<<<gq, 128>>>(x, W_qkv, b_qkv);

    dim3 ga(SEQ_N / 8, NHEAD);
    attn_kernel<<<ga, 256>>>(pos_bias, scale_e, if_gain, disp_amp);

    dim3 gg(DIM_D / BN, SEQ_N / BM);
    gemm_gate_kernel<<<gg, 128>>>(x, W_gate, b_gate);

    dim3 go(DIM_D / BN, SEQ_N / BM);
    gemm_out_kernel<<<go, 128>>>(W_out, b_out, out);
}

// round 4
// speedup vs baseline: 1.5621x; 1.5621x over previous
#include <cuda_runtime.h>
#include <cuda_bf16.h>
#include <math.h>
#include <stdint.h>

// ---------------------------------------------------------------------------
// B=1, N=2048, D=512, H=8, HD=64, NUM_OFFSETS=47
// ---------------------------------------------------------------------------
#define SEQ_N 2048
#define DIM_D 512
#define NHEAD 8
#define HDIM 64
#define NOFF 47

__constant__ int c_off[NOFF] = {
    0,1,2,3,4,5,6,7,8,9,10,11,12,13,14,15,16,17,18,19,20,21,22,23,24,25,26,
    27,28,29,30,31,32,48,64,96,128,192,256,384,512,768,1024,1536,2048,3072,4096
};

// Scratch (__device__ globals; cudaMalloc forbidden)
__device__ float g_qkv [SEQ_N * 3 * DIM_D];                    // 12 MB
__device__ float g_aout[SEQ_N * DIM_D];                        // 4 MB
__device__ __align__(16) __nv_bfloat16 g_xhi [SEQ_N * DIM_D];
__device__ __align__(16) __nv_bfloat16 g_xlo [SEQ_N * DIM_D];
__device__ __align__(16) __nv_bfloat16 g_ghi [SEQ_N * DIM_D];  // gated activation hi
__device__ __align__(16) __nv_bfloat16 g_glo [SEQ_N * DIM_D];
__device__ __align__(16) __nv_bfloat16 g_wqkv_hi[DIM_D * 3 * DIM_D];
__device__ __align__(16) __nv_bfloat16 g_wqkv_lo[DIM_D * 3 * DIM_D];
__device__ __align__(16) __nv_bfloat16 g_wg_hi[DIM_D * DIM_D];
__device__ __align__(16) __nv_bfloat16 g_wg_lo[DIM_D * DIM_D];
__device__ __align__(16) __nv_bfloat16 g_wo_hi[DIM_D * DIM_D];
__device__ __align__(16) __nv_bfloat16 g_wo_lo[DIM_D * DIM_D];

// ---------------------------------------------------------------------------
// fp32 -> bf16 hi/lo split conversion
// ---------------------------------------------------------------------------
__device__ __forceinline__ void cvt_body(const float* __restrict__ in,
                                         __nv_bfloat16* __restrict__ hi,
                                         __nv_bfloat16* __restrict__ lo, int n4)
{
    int i = blockIdx.x * blockDim.x + threadIdx.x;
    if (i >= n4) return;
    float4 v = ((const float4*)in)[i];
    __nv_bfloat16 h0 = __float2bfloat16(v.x);
    __nv_bfloat16 h1 = __float2bfloat16(v.y);
    __nv_bfloat16 h2 = __float2bfloat16(v.z);
    __nv_bfloat16 h3 = __float2bfloat16(v.w);
    __nv_bfloat162 hh0 = {h0, h1}, hh1 = {h2, h3};
    ((__nv_bfloat162*)hi)[i * 2 + 0] = hh0;
    ((__nv_bfloat162*)hi)[i * 2 + 1] = hh1;
    __nv_bfloat162 ll0 = {__float2bfloat16(v.x - __bfloat162float(h0)),
                          __float2bfloat16(v.y - __bfloat162float(h1))};
    __nv_bfloat162 ll1 = {__float2bfloat16(v.z - __bfloat162float(h2)),
                          __float2bfloat16(v.w - __bfloat162float(h3))};
    ((__nv_bfloat162*)lo)[i * 2 + 0] = ll0;
    ((__nv_bfloat162*)lo)[i * 2 + 1] = ll1;
}

__global__ void cvt_x_kernel   (const float* in){ cvt_body(in, g_xhi,    g_xlo,    SEQ_N * DIM_D / 4); }
__global__ void cvt_wqkv_kernel(const float* in){ cvt_body(in, g_wqkv_hi,g_wqkv_lo,DIM_D * 3 * DIM_D / 4); }
__global__ void cvt_wg_kernel  (const float* in){ cvt_body(in, g_wg_hi,  g_wg_lo,  DIM_D * DIM_D / 4); }
__global__ void cvt_wo_kernel  (const float* in){ cvt_body(in, g_wo_hi,  g_wo_lo,  DIM_D * DIM_D / 4); }

// ---------------------------------------------------------------------------
// bf16 split-precision MMA GEMM.
// C[M,N] = (Ahi+Alo)[M,K] @ (Bhi+Blo)[K,N]  via  hi*hi + hi*lo + lo*hi
// Block: 64x64 tile, BK=32, 4 warps (2x2), each warp 32x32.
// EPI 0: C = acc + bias  (fp32)
// EPI 1: v = g_aout * sigmoid(acc + bias); write bf16 split to Chi/Clo
// ---------------------------------------------------------------------------
#define GBM 64
#define GBN 64
#define GBK 32
#define ASTR 40   // sA row stride (bf16 elems): 32 + 8 pad
#define BSTR 72   // sB row stride: 64 + 8 pad

__device__ __forceinline__ uint32_t smem_u32(const void* p)
{
    return (uint32_t)__cvta_generic_to_shared(p);
}

__device__ __forceinline__ void ldsm_x4(uint32_t& r0, uint32_t& r1,
                                        uint32_t& r2, uint32_t& r3, uint32_t addr)
{
    asm volatile("ldmatrix.sync.aligned.m8n8.x4.shared.b16 {%0,%1,%2,%3},[%4];"
                 : "=r"(r0), "=r"(r1), "=r"(r2), "=r"(r3) : "r"(addr));
}

__device__ __forceinline__ void ldsm_x4_t(uint32_t& r0, uint32_t& r1,
                                          uint32_t& r2, uint32_t& r3, uint32_t addr)
{
    asm volatile("ldmatrix.sync.aligned.m8n8.x4.trans.shared.b16 {%0,%1,%2,%3},[%4];"
                 : "=r"(r0), "=r"(r1), "=r"(r2), "=r"(r3) : "r"(addr));
}

__device__ __forceinline__ void mma_bf16(float* c, const uint32_t* a, const uint32_t* b)
{
    asm volatile(
        "mma.sync.aligned.m16n8k16.row.col.f32.bf16.bf16.f32 "
        "{%0,%1,%2,%3},{%4,%5,%6,%7},{%8,%9},{%0,%1,%2,%3};"
        : "+f"(c[0]), "+f"(c[1]), "+f"(c[2]), "+f"(c[3])
        : "r"(a[0]), "r"(a[1]), "r"(a[2]), "r"(a[3]), "r"(b[0]), "r"(b[1]));
}

template<int EPI>
__device__ __forceinline__ void mma_gemm_body(
    const __nv_bfloat16* __restrict__ Ahi, const __nv_bfloat16* __restrict__ Alo,
    const __nv_bfloat16* __restrict__ Bhi, const __nv_bfloat16* __restrict__ Blo,
    const float* __restrict__ bias, float* __restrict__ C,
    __nv_bfloat16* __restrict__ Chi, __nv_bfloat16* __restrict__ Clo,
    int M, int N, int K)
{
    __shared__ __nv_bfloat16 sA[2][GBM][ASTR];
    __shared__ __nv_bfloat16 sB[2][GBK][BSTR];

    const int tid  = threadIdx.x;
    const int lane = tid & 31;
    const int warp = tid >> 5;
    const int wm = warp >> 1, wn = warp & 1;
    const int brow = blockIdx.y * GBM;
    const int bcol = blockIdx.x * GBN;

    // global->smem load mapping (128 threads)
    const int ar = tid >> 2;          // 0..31
    const int ak = (tid & 3) * 8;     // 0,8,16,24
    const int br = tid >> 3;          // 0..15
    const int bn = (tid & 7) * 8;     // 0..56

    float acc[2][4][4];
    #pragma unroll
    for (int i = 0; i < 2; i++)
        #pragma unroll
        for (int j = 0; j < 4; j++)
            #pragma unroll
            for (int t = 0; t < 4; t++) acc[i][j][t] = 0.f;

    for (int k0 = 0; k0 < K; k0 += GBK) {
        *(uint4*)&sA[0][ar     ][ak] = *(const uint4*)(Ahi + (size_t)(brow + ar     ) * K + k0 + ak);
        *(uint4*)&sA[0][ar + 32][ak] = *(const uint4*)(Ahi + (size_t)(brow + ar + 32) * K + k0 + ak);
        *(uint4*)&sA[1][ar     ][ak] = *(const uint4*)(Alo + (size_t)(brow + ar     ) * K + k0 + ak);
        *(uint4*)&sA[1][ar + 32][ak] = *(const uint4*)(Alo + (size_t)(brow + ar + 32) * K + k0 + ak);
        *(uint4*)&sB[0][br     ][bn] = *(const uint4*)(Bhi + (size_t)(k0 + br     ) * N + bcol + bn);
        *(uint4*)&sB[0][br + 16][bn] = *(const uint4*)(Bhi + (size_t)(k0 + br + 16) * N + bcol + bn);
        *(uint4*)&sB[1][br     ][bn] = *(const uint4*)(Blo + (size_t)(k0 + br     ) * N + bcol + bn);
        *(uint4*)&sB[1][br + 16][bn] = *(const uint4*)(Blo + (size_t)(k0 + br + 16) * N + bcol + bn);
        __syncthreads();

        #pragma unroll
        for (int kk = 0; kk < GBK; kk += 16) {
            uint32_t ahi[2][4], alo[2][4], bhi[4][2], blo[4][2];
            #pragma unroll
            for (int mt = 0; mt < 2; mt++) {
                const int row = wm * 32 + mt * 16 + (lane & 15);
                const int kof = kk + (lane >> 4) * 8;
                ldsm_x4(ahi[mt][0], ahi[mt][1], ahi[mt][2], ahi[mt][3],
                        smem_u32(&sA[0][row][kof]));
                ldsm_x4(alo[mt][0], alo[mt][1], alo[mt][2], alo[mt][3],
                        smem_u32(&sA[1][row][kof]));
            }
            #pragma unroll
            for (int np = 0; np < 2; np++) {
                const int krow = kk + (lane & 15);
                const int col  = wn * 32 + np * 16 + (lane >> 4) * 8;
                ldsm_x4_t(bhi[np*2][0], bhi[np*2][1], bhi[np*2+1][0], bhi[np*2+1][1],
                          smem_u32(&sB[0][krow][col]));
                ldsm_x4_t(blo[np*2][0], blo[np*2][1], blo[np*2+1][0], blo[np*2+1][1],
                          smem_u32(&sB[1][krow][col]));
            }
            #pragma unroll
            for (int mt = 0; mt < 2; mt++)
                #pragma unroll
                for (int nt = 0; nt < 4; nt++) {
                    mma_bf16(acc[mt][nt], ahi[mt], bhi[nt]);
                    mma_bf16(acc[mt][nt], ahi[mt], blo[nt]);
                    mma_bf16(acc[mt][nt], alo[mt], bhi[nt]);
                }
        }
        __syncthreads();
    }

    // epilogue
    const int gid = lane >> 2, tig = lane & 3;
    #pragma unroll
    for (int mt = 0; mt < 2; mt++) {
        #pragma unroll
        for (int nt = 0; nt < 4; nt++) {
            const int row = brow + wm * 32 + mt * 16 + gid;
            const int col = bcol + wn * 32 + nt * 8 + tig * 2;
            const float b0 = bias[col], b1 = bias[col + 1];
            float v00 = acc[mt][nt][0] + b0;
            float v01 = acc[mt][nt][1] + b1;
            float v10 = acc[mt][nt][2] + b0;
            float v11 = acc[mt][nt][3] + b1;
            if (EPI == 0) {
                float2 r0 = {v00, v01}, r1 = {v10, v11};
                *(float2*)(C + (size_t)row * N + col)       = r0;
                *(float2*)(C + (size_t)(row + 8) * N + col) = r1;
            } else {
                const float* ao = (const float*)g_aout;
                float2 a0 = *(const float2*)(ao + (size_t)row * N + col);
                float2 a1 = *(const float2*)(ao + (size_t)(row + 8) * N + col);
                v00 = a0.x / (1.f + __expf(-v00));
                v01 = a0.y / (1.f + __expf(-v01));
                v10 = a1.x / (1.f + __expf(-v10));
                v11 = a1.y / (1.f + __expf(-v11));
                __nv_bfloat16 h00 = __float2bfloat16(v00), h01 = __float2bfloat16(v01);
                __nv_bfloat16 h10 = __float2bfloat16(v10), h11 = __float2bfloat16(v11);
                __nv_bfloat162 hv0 = {h00, h01}, hv1 = {h10, h11};
                __nv_bfloat162 lv0 = {__float2bfloat16(v00 - __bfloat162float(h00)),
                                      __float2bfloat16(v01 - __bfloat162float(h01))};
                __nv_bfloat162 lv1 = {__float2bfloat16(v10 - __bfloat162float(h10)),
                                      __float2bfloat16(v11 - __bfloat162float(h11))};
                *(__nv_bfloat162*)(Chi + (size_t)row * N + col)       = hv0;
                *(__nv_bfloat162*)(Chi + (size_t)(row + 8) * N + col) = hv1;
                *(__nv_bfloat162*)(Clo + (size_t)row * N + col)       = lv0;
                *(__nv_bfloat162*)(Clo + (size_t)(row + 8) * N + col) = lv1;
            }
        }
    }
}

__global__ void __launch_bounds__(128) gemm_qkv_kernel(const float* __restrict__ bias)
{
    mma_gemm_body<0>(g_xhi, g_xlo, g_wqkv_hi, g_wqkv_lo, bias,
                     (float*)g_qkv, nullptr, nullptr, SEQ_N, 3 * DIM_D, DIM_D);
}

__global__ void __launch_bounds__(128) gemm_gate_kernel(const float* __restrict__ bias)
{
    mma_gemm_body<1>(g_xhi, g_xlo, g_wg_hi, g_wg_lo, bias,
                     nullptr, g_ghi, g_glo, SEQ_N, DIM_D, DIM_D);
}

__global__ void __launch_bounds__(128) gemm_out_kernel(const float* __restrict__ bias,
                                                       float* __restrict__ out)
{
    mma_gemm_body<0>(g_ghi, g_glo, g_wo_hi, g_wo_lo, bias,
                     out, nullptr, nullptr, SEQ_N, DIM_D, DIM_D);
}

// ---------------------------------------------------------------------------
// Attention: one warp per (token n, head h). Reads g_qkv, writes g_aout.
// (unchanged from the passing R3 kernel)
// ---------------------------------------------------------------------------
__global__ void __launch_bounds__(256) attn_kernel(
    const float* __restrict__ pos_bias,    // [47,8]
    const float* __restrict__ scale_embed, // [47,64]
    const float* __restrict__ if_gain,     // [8]
    const float* __restrict__ disp_amp)    // [8]
{
    const float* qkv = (const float*)g_qkv;
    const int warp = threadIdx.x >> 5;
    const int lane = threadIdx.x & 31;
    const int n = blockIdx.x * 8 + warp;
    const int h = blockIdx.y;
    const int d0 = lane * 2;

    const float* qrow = qkv + (size_t)n * (3 * DIM_D) + h * HDIM;
    float2 q = *(const float2*)(qrow + d0);
    q.x *= 0.125f;
    q.y *= 0.125f;

    const float LM    = logf(4097.0f);
    const float wbase = 3.14159265358979f / LM;
    const float om = (h < 2) ? 0.f : (h < 4) ? wbase : (h < 6) ? 4.f * wbase : 6.f * wbase;
    const float da = disp_amp[h];

    float eb0, eb1 = 0.f;
    {
        const int o = lane;
        float ck = (om > 0.f) ? cosf(om * logf(1.f + (float)c_off[o])) : 0.f;
        eb0 = pos_bias[o * NHEAD + h] + ck * da;
        const int o2 = lane + 32;
        if (o2 < NOFF) {
            float ck2 = (om > 0.f) ? cosf(om * logf(1.f + (float)c_off[o2])) : 0.f;
            eb1 = pos_bias[o2 * NHEAD + h] + ck2 * da;
        }
    }

    float s0 = -INFINITY, s1 = -INFINITY;

    for (int o = 0; o < NOFF; o++) {
        const int j = n - c_off[o];
        if (j < 0) break;
        const float* krow = qkv + (size_t)j * (3 * DIM_D) + DIM_D + h * HDIM;
        float2 kv = *(const float2*)(krow + d0);
        float2 se = *(const float2*)(scale_embed + o * HDIM + d0);
        float p = q.x * kv.x * (1.f + se.x) + q.y * kv.y * (1.f + se.y);
        p += __shfl_xor_sync(0xffffffffu, p, 16);
        p += __shfl_xor_sync(0xffffffffu, p, 8);
        p += __shfl_xor_sync(0xffffffffu, p, 4);
        p += __shfl_xor_sync(0xffffffffu, p, 2);
        p += __shfl_xor_sync(0xffffffffu, p, 1);
        if (o < 32) { if (lane == o)      s0 = p + eb0; }
        else        { if (lane == o - 32) s1 = p + eb1; }
    }

    float m = fmaxf(s0, s1);
    m = fmaxf(m, __shfl_xor_sync(0xffffffffu, m, 16));
    m = fmaxf(m, __shfl_xor_sync(0xffffffffu, m, 8));
    m = fmaxf(m, __shfl_xor_sync(0xffffffffu, m, 4));
    m = fmaxf(m, __shfl_xor_sync(0xffffffffu, m, 2));
    m = fmaxf(m, __shfl_xor_sync(0xffffffffu, m, 1));

    float e0 = __expf(s0 - m);
    float e1 = __expf(s1 - m);
    float z = e0 + e1;
    z += __shfl_xor_sync(0xffffffffu, z, 16);
    z += __shfl_xor_sync(0xffffffffu, z, 8);
    z += __shfl_xor_sync(0xffffffffu, z, 4);
    z += __shfl_xor_sync(0xffffffffu, z, 2);
    z += __shfl_xor_sync(0xffffffffu, z, 1);
    const float inv = 1.f / z;
    const float p0 = e0 * inv;
    const float p1 = e1 * inv;

    float2 acc = {0.f, 0.f};
    for (int o = 0; o < NOFF; o++) {
        const int j = n - c_off[o];
        if (j < 0) break;
        const float w = __shfl_sync(0xffffffffu, (o < 32) ? p0 : p1, o & 31);
        const float* vrow = qkv + (size_t)j * (3 * DIM_D) + 2 * DIM_D + h * HDIM;
        float2 vv = *(const float2*)(vrow + d0);
        acc.x = fmaf(w, vv.x, acc.x);
        acc.y = fmaf(w, vv.y, acc.y);
    }

    const float g = if_gain[h];
    float* aout = (float*)g_aout;
    float2 outv = {acc.x * g, acc.y * g};
    *(float2*)(aout + (size_t)n * DIM_D + h * HDIM + d0) = outv;
}

// ---------------------------------------------------------------------------
// Launch. Inputs: x, W_qkv, b_qkv, W_out, b_out, W_gate, b_gate, pos_bias,
// scale_embed, if_gain, disp_amp. Output: f32 [1,2048,512].
// ---------------------------------------------------------------------------
extern "C" void kernel_launch(void* const* d_in, const int* in_sizes, int n_in,
                              void* d_out, int out_size)
{
    const float* x        = (const float*)d_in[0];
    const float* W_qkv    = (const float*)d_in[1];
    const float* b_qkv    = (const float*)d_in[2];
    const float* W_out    = (const float*)d_in[3];
    const float* b_out    = (const float*)d_in[4];
    const float* W_gate   = (const float*)d_in[5];
    const float* b_gate   = (const float*)d_in[6];
    const float* pos_bias = (const float*)d_in[7];
    const float* scale_e  = (const float*)d_in[8];
    const float* if_gain  = (const float*)d_in[9];
    const float* disp_amp = (const float*)d_in[10];
    float* out = (float*)d_out;

    // fp32 -> bf16 hi/lo splits
    cvt_x_kernel   <<<(SEQ_N * DIM_D / 4 + 255) / 256, 256>>>(x);
    cvt_wqkv_kernel<<<(DIM_D * 3 * DIM_D / 4 + 255) / 256, 256>>>(W_qkv);
    cvt_wg_kernel  <<<(DIM_D * DIM_D / 4 + 255) / 256, 256>>>(W_gate);
    cvt_wo_kernel  <<<(DIM_D * DIM_D / 4 + 255) / 256, 256>>>(W_out);

    // 1) g_qkv = x @ W_qkv + b_qkv
    {
        dim3 grid((3 * DIM_D) / GBN, SEQ_N / GBM);
        gemm_qkv_kernel<<<grid, 128>>>(b_qkv);
    }
    // 2) attention
    {
        dim3 grid(SEQ_N / 8, NHEAD);
        attn_kernel<<<grid, 256>>>(pos_bias, scale_e, if_gain, disp_amp);
    }
    // 3) gated = aout * sigmoid(x @ W_gate + b_gate)  -> bf16 split
    {
        dim3 grid(DIM_D / GBN, SEQ_N / GBM);
        gemm_gate_kernel<<<grid, 128>>>(b_gate);
    }
    // 4) out = gated @ W_out + b_out
    {
        dim3 grid(DIM_D / GBN, SEQ_N / GBM);
        gemm_out_kernel<<<grid, 128>>>(b_out, out);
    }
}

// round 5
// speedup vs baseline: 1.5908x; 1.0183x over previous
#include <cuda_runtime.h>
#include <cuda_bf16.h>
#include <math.h>
#include <stdint.h>

#define SEQ_N 2048
#define DIM_D 512
#define NHEAD 8
#define HDIM 64
#define NOFF 47

__constant__ int c_off[NOFF] = {
    0,1,2,3,4,5,6,7,8,9,10,11,12,13,14,15,16,17,18,19,20,21,22,23,24,25,26,
    27,28,29,30,31,32,48,64,96,128,192,256,384,512,768,1024,1536,2048,3072,4096
};

// Scratch (__device__ globals)
__device__ float g_qkv [SEQ_N * 3 * DIM_D];
__device__ float g_aout[SEQ_N * DIM_D];
__device__ __align__(16) __nv_bfloat16 g_xhi [SEQ_N * DIM_D];
__device__ __align__(16) __nv_bfloat16 g_xlo [SEQ_N * DIM_D];
__device__ __align__(16) __nv_bfloat16 g_ghi [SEQ_N * DIM_D];
__device__ __align__(16) __nv_bfloat16 g_glo [SEQ_N * DIM_D];
__device__ __align__(16) __nv_bfloat16 g_wqkv_hi[DIM_D * 3 * DIM_D];
__device__ __align__(16) __nv_bfloat16 g_wqkv_lo[DIM_D * 3 * DIM_D];
__device__ __align__(16) __nv_bfloat16 g_wg_hi[DIM_D * DIM_D];
__device__ __align__(16) __nv_bfloat16 g_wg_lo[DIM_D * DIM_D];
__device__ __align__(16) __nv_bfloat16 g_wo_hi[DIM_D * DIM_D];
__device__ __align__(16) __nv_bfloat16 g_wo_lo[DIM_D * DIM_D];

// ---------------------------------------------------------------------------
// Fused fp32 -> bf16 hi/lo split for all four tensors (one launch).
// Regions in float4 units: x 262144 | wqkv 196608 | wg 65536 | wo 65536
// ---------------------------------------------------------------------------
__device__ __forceinline__ void cvt_one(const float* __restrict__ in,
                                        __nv_bfloat16* __restrict__ hi,
                                        __nv_bfloat16* __restrict__ lo, int i)
{
    float4 v = ((const float4*)in)[i];
    __nv_bfloat16 h0 = __float2bfloat16(v.x);
    __nv_bfloat16 h1 = __float2bfloat16(v.y);
    __nv_bfloat16 h2 = __float2bfloat16(v.z);
    __nv_bfloat16 h3 = __float2bfloat16(v.w);
    __nv_bfloat162 hh0 = {h0, h1}, hh1 = {h2, h3};
    ((__nv_bfloat162*)hi)[i * 2 + 0] = hh0;
    ((__nv_bfloat162*)hi)[i * 2 + 1] = hh1;
    __nv_bfloat162 ll0 = {__float2bfloat16(v.x - __bfloat162float(h0)),
                          __float2bfloat16(v.y - __bfloat162float(h1))};
    __nv_bfloat162 ll1 = {__float2bfloat16(v.z - __bfloat162float(h2)),
                          __float2bfloat16(v.w - __bfloat162float(h3))};
    ((__nv_bfloat162*)lo)[i * 2 + 0] = ll0;
    ((__nv_bfloat162*)lo)[i * 2 + 1] = ll1;
}

__global__ void __launch_bounds__(256) cvt_all_kernel(
    const float* __restrict__ x, const float* __restrict__ wqkv,
    const float* __restrict__ wg, const float* __restrict__ wo)
{
    const int i = blockIdx.x * 256 + threadIdx.x;
    if (i < 262144)       cvt_one(x,    g_xhi,     g_xlo,     i);
    else if (i < 458752)  cvt_one(wqkv, g_wqkv_hi, g_wqkv_lo, i - 262144);
    else if (i < 524288)  cvt_one(wg,   g_wg_hi,   g_wg_lo,   i - 458752);
    else if (i < 589824)  cvt_one(wo,   g_wo_hi,   g_wo_lo,   i - 524288);
}

// ---------------------------------------------------------------------------
// bf16 split MMA GEMM: C = (Ahi+Alo)@(Bhi+Blo) via hi*hi + hi*lo + lo*hi.
// Tile 128x64, GBK=16, 256 threads (8 warps, 4x2), warp tile 32x32.
// cp.async 2-stage double buffer. Static smem = 33792 B.
// EPI 0: C = acc + bias (fp32).  EPI 1: g_aout*sigmoid(acc+bias) -> Chi/Clo.
// ---------------------------------------------------------------------------
#define GBM 128
#define GBN 64
#define GBK 16
#define ASTR 24   // 16 + 8 pad (48B rows, 16B-aligned)
#define BSTR 72   // 64 + 8 pad

__device__ __forceinline__ uint32_t smem_u32(const void* p)
{
    return (uint32_t)__cvta_generic_to_shared(p);
}

__device__ __forceinline__ void cp16(void* dst, const void* src)
{
    asm volatile("cp.async.cg.shared.global [%0], [%1], 16;\n"
                 :: "r"(smem_u32(dst)), "l"(src));
}

__device__ __forceinline__ void ldsm_x4(uint32_t& r0, uint32_t& r1,
                                        uint32_t& r2, uint32_t& r3, uint32_t addr)
{
    asm volatile("ldmatrix.sync.aligned.m8n8.x4.shared.b16 {%0,%1,%2,%3},[%4];"
                 : "=r"(r0), "=r"(r1), "=r"(r2), "=r"(r3) : "r"(addr));
}

__device__ __forceinline__ void ldsm_x4_t(uint32_t& r0, uint32_t& r1,
                                          uint32_t& r2, uint32_t& r3, uint32_t addr)
{
    asm volatile("ldmatrix.sync.aligned.m8n8.x4.trans.shared.b16 {%0,%1,%2,%3},[%4];"
                 : "=r"(r0), "=r"(r1), "=r"(r2), "=r"(r3) : "r"(addr));
}

__device__ __forceinline__ void mma_bf16(float* c, const uint32_t* a, const uint32_t* b)
{
    asm volatile(
        "mma.sync.aligned.m16n8k16.row.col.f32.bf16.bf16.f32 "
        "{%0,%1,%2,%3},{%4,%5,%6,%7},{%8,%9},{%0,%1,%2,%3};"
        : "+f"(c[0]), "+f"(c[1]), "+f"(c[2]), "+f"(c[3])
        : "r"(a[0]), "r"(a[1]), "r"(a[2]), "r"(a[3]), "r"(b[0]), "r"(b[1]));
}

template<int EPI>
__device__ __forceinline__ void mma_gemm_body(
    const __nv_bfloat16* __restrict__ Ahi, const __nv_bfloat16* __restrict__ Alo,
    const __nv_bfloat16* __restrict__ Bhi, const __nv_bfloat16* __restrict__ Blo,
    const float* __restrict__ bias, float* __restrict__ C,
    __nv_bfloat16* __restrict__ Chi, __nv_bfloat16* __restrict__ Clo,
    int M, int N, int K)
{
    __shared__ __nv_bfloat16 sA[2][2][GBM][ASTR];  // [stage][hi/lo]
    __shared__ __nv_bfloat16 sB[2][2][GBK][BSTR];

    const int tid  = threadIdx.x;
    const int lane = tid & 31;
    const int warp = tid >> 5;
    const int wm = warp >> 1, wn = warp & 1;
    const int brow = blockIdx.y * GBM;
    const int bcol = blockIdx.x * GBN;

    // cp.async mappings
    // A: 512 chunks (2 mats x 128 rows x 2), thread handles c = tid, tid+256
    const int a0_mat = 0,               a0_rem = tid;
    const int a1_mat = 1,               a1_rem = tid;          // tid+256 -> mat 1, rem tid
    const int ar0 = a0_rem >> 1, ac0 = (a0_rem & 1) * 8;
    const int ar1 = a1_rem >> 1, ac1 = (a1_rem & 1) * 8;
    // B: 256 chunks (2 mats x 16 rows x 8)
    const int b_mat = tid >> 7;
    const int b_rem = tid & 127;
    const int b_row = b_rem >> 3, b_col = (b_rem & 7) * 8;
    (void)a0_mat; (void)a1_mat;

    float acc[2][4][4];
    #pragma unroll
    for (int i = 0; i < 2; i++)
        #pragma unroll
        for (int j = 0; j < 4; j++)
            #pragma unroll
            for (int t = 0; t < 4; t++) acc[i][j][t] = 0.f;

    auto load_stage = [&](int stage, int k0) {
        cp16(&sA[stage][0][ar0][ac0], Ahi + (size_t)(brow + ar0) * K + k0 + ac0);
        cp16(&sA[stage][1][ar1][ac1], Alo + (size_t)(brow + ar1) * K + k0 + ac1);
        const __nv_bfloat16* bsrc = (b_mat ? Blo : Bhi) + (size_t)(k0 + b_row) * N + bcol + b_col;
        cp16(&sB[stage][b_mat][b_row][b_col], bsrc);
        asm volatile("cp.async.commit_group;\n" ::);
    };

    load_stage(0, 0);
    int stage = 0;
    for (int k0 = 0; k0 < K; k0 += GBK) {
        if (k0 + GBK < K) {
            load_stage(stage ^ 1, k0 + GBK);
            asm volatile("cp.async.wait_group 1;\n" ::);
        } else {
            asm volatile("cp.async.wait_group 0;\n" ::);
        }
        __syncthreads();

        // compute one k16 chunk from 'stage'
        uint32_t ahi[2][4], alo[2][4], bhi[4][2], blo[4][2];
        #pragma unroll
        for (int mt = 0; mt < 2; mt++) {
            const int row = wm * 32 + mt * 16 + (lane & 15);
            const int kof = (lane >> 4) * 8;
            ldsm_x4(ahi[mt][0], ahi[mt][1], ahi[mt][2], ahi[mt][3],
                    smem_u32(&sA[stage][0][row][kof]));
            ldsm_x4(alo[mt][0], alo[mt][1], alo[mt][2], alo[mt][3],
                    smem_u32(&sA[stage][1][row][kof]));
        }
        #pragma unroll
        for (int np = 0; np < 2; np++) {
            const int krow = lane & 15;
            const int col  = wn * 32 + np * 16 + (lane >> 4) * 8;
            ldsm_x4_t(bhi[np*2][0], bhi[np*2][1], bhi[np*2+1][0], bhi[np*2+1][1],
                      smem_u32(&sB[stage][0][krow][col]));
            ldsm_x4_t(blo[np*2][0], blo[np*2][1], blo[np*2+1][0], blo[np*2+1][1],
                      smem_u32(&sB[stage][1][krow][col]));
        }
        #pragma unroll
        for (int mt = 0; mt < 2; mt++)
            #pragma unroll
            for (int nt = 0; nt < 4; nt++) {
                mma_bf16(acc[mt][nt], ahi[mt], bhi[nt]);
                mma_bf16(acc[mt][nt], ahi[mt], blo[nt]);
                mma_bf16(acc[mt][nt], alo[mt], bhi[nt]);
            }
        __syncthreads();
        stage ^= 1;
    }

    // epilogue
    const int gid = lane >> 2, tig = lane & 3;
    #pragma unroll
    for (int mt = 0; mt < 2; mt++) {
        #pragma unroll
        for (int nt = 0; nt < 4; nt++) {
            const int row = brow + wm * 32 + mt * 16 + gid;
            const int col = bcol + wn * 32 + nt * 8 + tig * 2;
            const float b0 = bias[col], b1 = bias[col + 1];
            float v00 = acc[mt][nt][0] + b0;
            float v01 = acc[mt][nt][1] + b1;
            float v10 = acc[mt][nt][2] + b0;
            float v11 = acc[mt][nt][3] + b1;
            if (EPI == 0) {
                float2 r0 = {v00, v01}, r1 = {v10, v11};
                *(float2*)(C + (size_t)row * N + col)       = r0;
                *(float2*)(C + (size_t)(row + 8) * N + col) = r1;
            } else {
                const float* ao = (const float*)g_aout;
                float2 a0 = *(const float2*)(ao + (size_t)row * N + col);
                float2 a1 = *(const float2*)(ao + (size_t)(row + 8) * N + col);
                v00 = a0.x / (1.f + __expf(-v00));
                v01 = a0.y / (1.f + __expf(-v01));
                v10 = a1.x / (1.f + __expf(-v10));
                v11 = a1.y / (1.f + __expf(-v11));
                __nv_bfloat16 h00 = __float2bfloat16(v00), h01 = __float2bfloat16(v01);
                __nv_bfloat16 h10 = __float2bfloat16(v10), h11 = __float2bfloat16(v11);
                __nv_bfloat162 hv0 = {h00, h01}, hv1 = {h10, h11};
                __nv_bfloat162 lv0 = {__float2bfloat16(v00 - __bfloat162float(h00)),
                                      __float2bfloat16(v01 - __bfloat162float(h01))};
                __nv_bfloat162 lv1 = {__float2bfloat16(v10 - __bfloat162float(h10)),
                                      __float2bfloat16(v11 - __bfloat162float(h11))};
                *(__nv_bfloat162*)(Chi + (size_t)row * N + col)       = hv0;
                *(__nv_bfloat162*)(Chi + (size_t)(row + 8) * N + col) = hv1;
                *(__nv_bfloat162*)(Clo + (size_t)row * N + col)       = lv0;
                *(__nv_bfloat162*)(Clo + (size_t)(row + 8) * N + col) = lv1;
            }
        }
    }
}

__global__ void __launch_bounds__(256) gemm_qkv_kernel(const float* __restrict__ bias)
{
    mma_gemm_body<0>(g_xhi, g_xlo, g_wqkv_hi, g_wqkv_lo, bias,
                     (float*)g_qkv, nullptr, nullptr, SEQ_N, 3 * DIM_D, DIM_D);
}

__global__ void __launch_bounds__(256) gemm_gate_kernel(const float* __restrict__ bias)
{
    mma_gemm_body<1>(g_xhi, g_xlo, g_wg_hi, g_wg_lo, bias,
                     nullptr, g_ghi, g_glo, SEQ_N, DIM_D, DIM_D);
}

__global__ void __launch_bounds__(256) gemm_out_kernel(const float* __restrict__ bias,
                                                       float* __restrict__ out)
{
    mma_gemm_body<0>(g_ghi, g_glo, g_wo_hi, g_wo_lo, bias,
                     out, nullptr, nullptr, SEQ_N, DIM_D, DIM_D);
}

// ---------------------------------------------------------------------------
// Attention: one warp per (token n, head h). Reads g_qkv, writes g_aout.
// ---------------------------------------------------------------------------
__global__ void __launch_bounds__(256) attn_kernel(
    const float* __restrict__ pos_bias,
    const float* __restrict__ scale_embed,
    const float* __restrict__ if_gain,
    const float* __restrict__ disp_amp)
{
    const float* qkv = (const float*)g_qkv;
    const int warp = threadIdx.x >> 5;
    const int lane = threadIdx.x & 31;
    const int n = blockIdx.x * 8 + warp;
    const int h = blockIdx.y;
    const int d0 = lane * 2;

    const float* qrow = qkv + (size_t)n * (3 * DIM_D) + h * HDIM;
    float2 q = *(const float2*)(qrow + d0);
    q.x *= 0.125f;
    q.y *= 0.125f;

    const float LM    = logf(4097.0f);
    const float wbase = 3.14159265358979f / LM;
    const float om = (h < 2) ? 0.f : (h < 4) ? wbase : (h < 6) ? 4.f * wbase : 6.f * wbase;
    const float da = disp_amp[h];

    float eb0, eb1 = 0.f;
    {
        const int o = lane;
        float ck = (om > 0.f) ? cosf(om * logf(1.f + (float)c_off[o])) : 0.f;
        eb0 = pos_bias[o * NHEAD + h] + ck * da;
        const int o2 = lane + 32;
        if (o2 < NOFF) {
            float ck2 = (om > 0.f) ? cosf(om * logf(1.f + (float)c_off[o2])) : 0.f;
            eb1 = pos_bias[o2 * NHEAD + h] + ck2 * da;
        }
    }

    float s0 = -INFINITY, s1 = -INFINITY;

    for (int o = 0; o < NOFF; o++) {
        const int j = n - c_off[o];
        if (j < 0) break;
        const float* krow = qkv + (size_t)j * (3 * DIM_D) + DIM_D + h * HDIM;
        float2 kv = *(const float2*)(krow + d0);
        float2 se = *(const float2*)(scale_embed + o * HDIM + d0);
        float p = q.x * kv.x * (1.f + se.x) + q.y * kv.y * (1.f + se.y);
        p += __shfl_xor_sync(0xffffffffu, p, 16);
        p += __shfl_xor_sync(0xffffffffu, p, 8);
        p += __shfl_xor_sync(0xffffffffu, p, 4);
        p += __shfl_xor_sync(0xffffffffu, p, 2);
        p += __shfl_xor_sync(0xffffffffu, p, 1);
        if (o < 32) { if (lane == o)      s0 = p + eb0; }
        else        { if (lane == o - 32) s1 = p + eb1; }
    }

    float m = fmaxf(s0, s1);
    m = fmaxf(m, __shfl_xor_sync(0xffffffffu, m, 16));
    m = fmaxf(m, __shfl_xor_sync(0xffffffffu, m, 8));
    m = fmaxf(m, __shfl_xor_sync(0xffffffffu, m, 4));
    m = fmaxf(m, __shfl_xor_sync(0xffffffffu, m, 2));
    m = fmaxf(m, __shfl_xor_sync(0xffffffffu, m, 1));

    float e0 = __expf(s0 - m);
    float e1 = __expf(s1 - m);
    float z = e0 + e1;
    z += __shfl_xor_sync(0xffffffffu, z, 16);
    z += __shfl_xor_sync(0xffffffffu, z, 8);
    z += __shfl_xor_sync(0xffffffffu, z, 4);
    z += __shfl_xor_sync(0xffffffffu, z, 2);
    z += __shfl_xor_sync(0xffffffffu, z, 1);
    const float inv = 1.f / z;
    const float p0 = e0 * inv;
    const float p1 = e1 * inv;

    float2 acc = {0.f, 0.f};
    for (int o = 0; o < NOFF; o++) {
        const int j = n - c_off[o];
        if (j < 0) break;
        const float w = __shfl_sync(0xffffffffu, (o < 32) ? p0 : p1, o & 31);
        const float* vrow = qkv + (size_t)j * (3 * DIM_D) + 2 * DIM_D + h * HDIM;
        float2 vv = *(const float2*)(vrow + d0);
        acc.x = fmaf(w, vv.x, acc.x);
        acc.y = fmaf(w, vv.y, acc.y);
    }

    const float g = if_gain[h];
    float* aout = (float*)g_aout;
    float2 outv = {acc.x * g, acc.y * g};
    *(float2*)(aout + (size_t)n * DIM_D + h * HDIM + d0) = outv;
}

// ---------------------------------------------------------------------------
extern "C" void kernel_launch(void* const* d_in, const int* in_sizes, int n_in,
                              void* d_out, int out_size)
{
    const float* x        = (const float*)d_in[0];
    const float* W_qkv    = (const float*)d_in[1];
    const float* b_qkv    = (const float*)d_in[2];
    const float* W_out    = (const float*)d_in[3];
    const float* b_out    = (const float*)d_in[4];
    const float* W_gate   = (const float*)d_in[5];
    const float* b_gate   = (const float*)d_in[6];
    const float* pos_bias = (const float*)d_in[7];
    const float* scale_e  = (const float*)d_in[8];
    const float* if_gain  = (const float*)d_in[9];
    const float* disp_amp = (const float*)d_in[10];
    float* out = (float*)d_out;

    cvt_all_kernel<<<2304, 256>>>(x, W_qkv, W_gate, W_out);

    {
        dim3 grid((3 * DIM_D) / GBN, SEQ_N / GBM);   // 24 x 16
        gemm_qkv_kernel<<<grid, 256>>>(b_qkv);
    }
    {
        dim3 grid(SEQ_N / 8, NHEAD);
        attn_kernel<<<grid, 256>>>(pos_bias, scale_e, if_gain, disp_amp);
    }
    {
        dim3 grid(DIM_D / GBN, SEQ_N / GBM);         // 8 x 16
        gemm_gate_kernel<<<grid, 256>>>(b_gate);
    }
    {
        dim3 grid(DIM_D / GBN, SEQ_N / GBM);
        gemm_out_kernel<<<grid, 256>>>(b_out, out);
    }
}

// round 6
// speedup vs baseline: 1.7581x; 1.1052x over previous
#include <cuda_runtime.h>
#include <cuda_bf16.h>
#include <math.h>
#include <stdint.h>

#define SEQ_N 2048
#define DIM_D 512
#define NHEAD 8
#define HDIM 64
#define NOFF 47

__constant__ int c_off[NOFF] = {
    0,1,2,3,4,5,6,7,8,9,10,11,12,13,14,15,16,17,18,19,20,21,22,23,24,25,26,
    27,28,29,30,31,32,48,64,96,128,192,256,384,512,768,1024,1536,2048,3072,4096
};

// Scratch (__device__ globals)
__device__ float g_qkv [SEQ_N * 3 * DIM_D];
__device__ float g_aout[SEQ_N * DIM_D];
__device__ __align__(16) __nv_bfloat16 g_xhi [SEQ_N * DIM_D];
__device__ __align__(16) __nv_bfloat16 g_xlo [SEQ_N * DIM_D];
__device__ __align__(16) __nv_bfloat16 g_ghi [SEQ_N * DIM_D];
__device__ __align__(16) __nv_bfloat16 g_glo [SEQ_N * DIM_D];
__device__ __align__(16) __nv_bfloat16 g_wqkv_hi[DIM_D * 3 * DIM_D];
__device__ __align__(16) __nv_bfloat16 g_wqkv_lo[DIM_D * 3 * DIM_D];
__device__ __align__(16) __nv_bfloat16 g_wg_hi[DIM_D * DIM_D];
__device__ __align__(16) __nv_bfloat16 g_wg_lo[DIM_D * DIM_D];
__device__ __align__(16) __nv_bfloat16 g_wo_hi[DIM_D * DIM_D];
__device__ __align__(16) __nv_bfloat16 g_wo_lo[DIM_D * DIM_D];

// ---------------------------------------------------------------------------
// Fused fp32 -> bf16 hi/lo split (one launch).
// float4 regions: x 262144 | wqkv 196608 | wg 65536 | wo 65536
// ---------------------------------------------------------------------------
__device__ __forceinline__ void cvt_one(const float* __restrict__ in,
                                        __nv_bfloat16* __restrict__ hi,
                                        __nv_bfloat16* __restrict__ lo, int i)
{
    float4 v = ((const float4*)in)[i];
    __nv_bfloat16 h0 = __float2bfloat16(v.x);
    __nv_bfloat16 h1 = __float2bfloat16(v.y);
    __nv_bfloat16 h2 = __float2bfloat16(v.z);
    __nv_bfloat16 h3 = __float2bfloat16(v.w);
    __nv_bfloat162 hh0 = {h0, h1}, hh1 = {h2, h3};
    ((__nv_bfloat162*)hi)[i * 2 + 0] = hh0;
    ((__nv_bfloat162*)hi)[i * 2 + 1] = hh1;
    __nv_bfloat162 ll0 = {__float2bfloat16(v.x - __bfloat162float(h0)),
                          __float2bfloat16(v.y - __bfloat162float(h1))};
    __nv_bfloat162 ll1 = {__float2bfloat16(v.z - __bfloat162float(h2)),
                          __float2bfloat16(v.w - __bfloat162float(h3))};
    ((__nv_bfloat162*)lo)[i * 2 + 0] = ll0;
    ((__nv_bfloat162*)lo)[i * 2 + 1] = ll1;
}

__global__ void __launch_bounds__(256) cvt_all_kernel(
    const float* __restrict__ x, const float* __restrict__ wqkv,
    const float* __restrict__ wg, const float* __restrict__ wo)
{
    const int i = blockIdx.x * 256 + threadIdx.x;
    if (i < 262144)       cvt_one(x,    g_xhi,     g_xlo,     i);
    else if (i < 458752)  cvt_one(wqkv, g_wqkv_hi, g_wqkv_lo, i - 262144);
    else if (i < 524288)  cvt_one(wg,   g_wg_hi,   g_wg_lo,   i - 458752);
    else if (i < 589824)  cvt_one(wo,   g_wo_hi,   g_wo_lo,   i - 524288);
}

// ---------------------------------------------------------------------------
// bf16 split MMA GEMM: C = (Ahi+Alo)@(Bhi+Blo) via hi*hi + hi*lo + lo*hi.
// Tile 64x64, GBK=32, 128 threads (4 warps 2x2, warp 32x32).
// 2-stage cp.async double buffer; 48 MMAs per sync window.
// EPI 0: C = acc + bias (fp32).  EPI 1: g_aout*sigmoid(acc+bias) -> Chi/Clo.
// ---------------------------------------------------------------------------
#define GBM 64
#define GBN 64
#define GBK 32
#define ASTR 40   // 32 + 8 pad
#define BSTR 72   // 64 + 8 pad

__device__ __forceinline__ uint32_t smem_u32(const void* p)
{
    return (uint32_t)__cvta_generic_to_shared(p);
}

__device__ __forceinline__ void cp16(void* dst, const void* src)
{
    asm volatile("cp.async.cg.shared.global [%0], [%1], 16;\n"
                 :: "r"(smem_u32(dst)), "l"(src));
}

__device__ __forceinline__ void ldsm_x4(uint32_t& r0, uint32_t& r1,
                                        uint32_t& r2, uint32_t& r3, uint32_t addr)
{
    asm volatile("ldmatrix.sync.aligned.m8n8.x4.shared.b16 {%0,%1,%2,%3},[%4];"
                 : "=r"(r0), "=r"(r1), "=r"(r2), "=r"(r3) : "r"(addr));
}

__device__ __forceinline__ void ldsm_x4_t(uint32_t& r0, uint32_t& r1,
                                          uint32_t& r2, uint32_t& r3, uint32_t addr)
{
    asm volatile("ldmatrix.sync.aligned.m8n8.x4.trans.shared.b16 {%0,%1,%2,%3},[%4];"
                 : "=r"(r0), "=r"(r1), "=r"(r2), "=r"(r3) : "r"(addr));
}

__device__ __forceinline__ void mma_bf16(float* c, const uint32_t* a, const uint32_t* b)
{
    asm volatile(
        "mma.sync.aligned.m16n8k16.row.col.f32.bf16.bf16.f32 "
        "{%0,%1,%2,%3},{%4,%5,%6,%7},{%8,%9},{%0,%1,%2,%3};"
        : "+f"(c[0]), "+f"(c[1]), "+f"(c[2]), "+f"(c[3])
        : "r"(a[0]), "r"(a[1]), "r"(a[2]), "r"(a[3]), "r"(b[0]), "r"(b[1]));
}

template<int EPI>
__device__ __forceinline__ void mma_gemm_body(
    const __nv_bfloat16* __restrict__ Ahi, const __nv_bfloat16* __restrict__ Alo,
    const __nv_bfloat16* __restrict__ Bhi, const __nv_bfloat16* __restrict__ Blo,
    const float* __restrict__ bias, float* __restrict__ C,
    __nv_bfloat16* __restrict__ Chi, __nv_bfloat16* __restrict__ Clo,
    int M, int N, int K)
{
    __shared__ __nv_bfloat16 sA[2][2][GBM][ASTR];  // [stage][hi/lo]
    __shared__ __nv_bfloat16 sB[2][2][GBK][BSTR];

    const int tid  = threadIdx.x;
    const int lane = tid & 31;
    const int warp = tid >> 5;
    const int wm = warp >> 1, wn = warp & 1;
    const int brow = blockIdx.y * GBM;
    const int bcol = blockIdx.x * GBN;

    float acc[2][4][4];
    #pragma unroll
    for (int i = 0; i < 2; i++)
        #pragma unroll
        for (int j = 0; j < 4; j++)
            #pragma unroll
            for (int t = 0; t < 4; t++) acc[i][j][t] = 0.f;

    auto load_stage = [&](int stage, int k0) {
        // A: 512 chunks of 8 bf16 (2 mats x 64 rows x 4), 4 per thread
        #pragma unroll
        for (int i = 0; i < 4; i++) {
            const int c   = tid + i * 128;
            const int mat = c >> 8;
            const int rem = c & 255;
            const int row = rem >> 2;
            const int kc  = (rem & 3) * 8;
            const __nv_bfloat16* src = (mat ? Alo : Ahi) + (size_t)(brow + row) * K + k0 + kc;
            cp16(&sA[stage][mat][row][kc], src);
        }
        // B: 512 chunks (2 mats x 32 rows x 8), 4 per thread
        #pragma unroll
        for (int i = 0; i < 4; i++) {
            const int c   = tid + i * 128;
            const int mat = c >> 8;
            const int rem = c & 255;
            const int row = rem >> 3;
            const int col = (rem & 7) * 8;
            const __nv_bfloat16* src = (mat ? Blo : Bhi) + (size_t)(k0 + row) * N + bcol + col;
            cp16(&sB[stage][mat][row][col], src);
        }
        asm volatile("cp.async.commit_group;\n" ::);
    };

    load_stage(0, 0);
    int stage = 0;
    for (int k0 = 0; k0 < K; k0 += GBK) {
        if (k0 + GBK < K) {
            load_stage(stage ^ 1, k0 + GBK);
            asm volatile("cp.async.wait_group 1;\n" ::);
        } else {
            asm volatile("cp.async.wait_group 0;\n" ::);
        }
        __syncthreads();

        #pragma unroll
        for (int kk = 0; kk < GBK; kk += 16) {
            uint32_t ahi[2][4], alo[2][4], bhi[4][2], blo[4][2];
            #pragma unroll
            for (int mt = 0; mt < 2; mt++) {
                const int row = wm * 32 + mt * 16 + (lane & 15);
                const int kof = kk + (lane >> 4) * 8;
                ldsm_x4(ahi[mt][0], ahi[mt][1], ahi[mt][2], ahi[mt][3],
                        smem_u32(&sA[stage][0][row][kof]));
                ldsm_x4(alo[mt][0], alo[mt][1], alo[mt][2], alo[mt][3],
                        smem_u32(&sA[stage][1][row][kof]));
            }
            #pragma unroll
            for (int np = 0; np < 2; np++) {
                const int krow = kk + (lane & 15);
                const int col  = wn * 32 + np * 16 + (lane >> 4) * 8;
                ldsm_x4_t(bhi[np*2][0], bhi[np*2][1], bhi[np*2+1][0], bhi[np*2+1][1],
                          smem_u32(&sB[stage][0][krow][col]));
                ldsm_x4_t(blo[np*2][0], blo[np*2][1], blo[np*2+1][0], blo[np*2+1][1],
                          smem_u32(&sB[stage][1][krow][col]));
            }
            #pragma unroll
            for (int mt = 0; mt < 2; mt++)
                #pragma unroll
                for (int nt = 0; nt < 4; nt++) {
                    mma_bf16(acc[mt][nt], ahi[mt], bhi[nt]);
                    mma_bf16(acc[mt][nt], ahi[mt], blo[nt]);
                    mma_bf16(acc[mt][nt], alo[mt], bhi[nt]);
                }
        }
        __syncthreads();
        stage ^= 1;
    }

    // epilogue
    const int gid = lane >> 2, tig = lane & 3;
    #pragma unroll
    for (int mt = 0; mt < 2; mt++) {
        #pragma unroll
        for (int nt = 0; nt < 4; nt++) {
            const int row = brow + wm * 32 + mt * 16 + gid;
            const int col = bcol + wn * 32 + nt * 8 + tig * 2;
            const float b0 = bias[col], b1 = bias[col + 1];
            float v00 = acc[mt][nt][0] + b0;
            float v01 = acc[mt][nt][1] + b1;
            float v10 = acc[mt][nt][2] + b0;
            float v11 = acc[mt][nt][3] + b1;
            if (EPI == 0) {
                float2 r0 = {v00, v01}, r1 = {v10, v11};
                *(float2*)(C + (size_t)row * N + col)       = r0;
                *(float2*)(C + (size_t)(row + 8) * N + col) = r1;
            } else {
                const float* ao = (const float*)g_aout;
                float2 a0 = *(const float2*)(ao + (size_t)row * N + col);
                float2 a1 = *(const float2*)(ao + (size_t)(row + 8) * N + col);
                v00 = a0.x / (1.f + __expf(-v00));
                v01 = a0.y / (1.f + __expf(-v01));
                v10 = a1.x / (1.f + __expf(-v10));
                v11 = a1.y / (1.f + __expf(-v11));
                __nv_bfloat16 h00 = __float2bfloat16(v00), h01 = __float2bfloat16(v01);
                __nv_bfloat16 h10 = __float2bfloat16(v10), h11 = __float2bfloat16(v11);
                __nv_bfloat162 hv0 = {h00, h01}, hv1 = {h10, h11};
                __nv_bfloat162 lv0 = {__float2bfloat16(v00 - __bfloat162float(h00)),
                                      __float2bfloat16(v01 - __bfloat162float(h01))};
                __nv_bfloat162 lv1 = {__float2bfloat16(v10 - __bfloat162float(h10)),
                                      __float2bfloat16(v11 - __bfloat162float(h11))};
                *(__nv_bfloat162*)(Chi + (size_t)row * N + col)       = hv0;
                *(__nv_bfloat162*)(Chi + (size_t)(row + 8) * N + col) = hv1;
                *(__nv_bfloat162*)(Clo + (size_t)row * N + col)       = lv0;
                *(__nv_bfloat162*)(Clo + (size_t)(row + 8) * N + col) = lv1;
            }
        }
    }
}

__global__ void __launch_bounds__(128) gemm_qkv_kernel(const float* __restrict__ bias)
{
    mma_gemm_body<0>(g_xhi, g_xlo, g_wqkv_hi, g_wqkv_lo, bias,
                     (float*)g_qkv, nullptr, nullptr, SEQ_N, 3 * DIM_D, DIM_D);
}

__global__ void __launch_bounds__(128) gemm_gate_kernel(const float* __restrict__ bias)
{
    mma_gemm_body<1>(g_xhi, g_xlo, g_wg_hi, g_wg_lo, bias,
                     nullptr, g_ghi, g_glo, SEQ_N, DIM_D, DIM_D);
}

__global__ void __launch_bounds__(128) gemm_out_kernel(const float* __restrict__ bias,
                                                       float* __restrict__ out)
{
    mma_gemm_body<0>(g_ghi, g_glo, g_wo_hi, g_wo_lo, bias,
                     out, nullptr, nullptr, SEQ_N, DIM_D, DIM_D);
}

// ---------------------------------------------------------------------------
// Attention: one warp per (token n, head h).
// ---------------------------------------------------------------------------
__global__ void __launch_bounds__(256) attn_kernel(
    const float* __restrict__ pos_bias,
    const float* __restrict__ scale_embed,
    const float* __restrict__ if_gain,
    const float* __restrict__ disp_amp)
{
    const float* qkv = (const float*)g_qkv;
    const int warp = threadIdx.x >> 5;
    const int lane = threadIdx.x & 31;
    const int n = blockIdx.x * 8 + warp;
    const int h = blockIdx.y;
    const int d0 = lane * 2;

    const float* qrow = qkv + (size_t)n * (3 * DIM_D) + h * HDIM;
    float2 q = *(const float2*)(qrow + d0);
    q.x *= 0.125f;
    q.y *= 0.125f;

    const float LM    = logf(4097.0f);
    const float wbase = 3.14159265358979f / LM;
    const float om = (h < 2) ? 0.f : (h < 4) ? wbase : (h < 6) ? 4.f * wbase : 6.f * wbase;
    const float da = disp_amp[h];

    float eb0, eb1 = 0.f;
    {
        const int o = lane;
        float ck = (om > 0.f) ? cosf(om * logf(1.f + (float)c_off[o])) : 0.f;
        eb0 = pos_bias[o * NHEAD + h] + ck * da;
        const int o2 = lane + 32;
        if (o2 < NOFF) {
            float ck2 = (om > 0.f) ? cosf(om * logf(1.f + (float)c_off[o2])) : 0.f;
            eb1 = pos_bias[o2 * NHEAD + h] + ck2 * da;
        }
    }

    float s0 = -INFINITY, s1 = -INFINITY;

    for (int o = 0; o < NOFF; o++) {
        const int j = n - c_off[o];
        if (j < 0) break;
        const float* krow = qkv + (size_t)j * (3 * DIM_D) + DIM_D + h * HDIM;
        float2 kv = *(const float2*)(krow + d0);
        float2 se = *(const float2*)(scale_embed + o * HDIM + d0);
        float p = q.x * kv.x * (1.f + se.x) + q.y * kv.y * (1.f + se.y);
        p += __shfl_xor_sync(0xffffffffu, p, 16);
        p += __shfl_xor_sync(0xffffffffu, p, 8);
        p += __shfl_xor_sync(0xffffffffu, p, 4);
        p += __shfl_xor_sync(0xffffffffu, p, 2);
        p += __shfl_xor_sync(0xffffffffu, p, 1);
        if (o < 32) { if (lane == o)      s0 = p + eb0; }
        else        { if (lane == o - 32) s1 = p + eb1; }
    }

    float m = fmaxf(s0, s1);
    m = fmaxf(m, __shfl_xor_sync(0xffffffffu, m, 16));
    m = fmaxf(m, __shfl_xor_sync(0xffffffffu, m, 8));
    m = fmaxf(m, __shfl_xor_sync(0xffffffffu, m, 4));
    m = fmaxf(m, __shfl_xor_sync(0xffffffffu, m, 2));
    m = fmaxf(m, __shfl_xor_sync(0xffffffffu, m, 1));

    float e0 = __expf(s0 - m);
    float e1 = __expf(s1 - m);
    float z = e0 + e1;
    z += __shfl_xor_sync(0xffffffffu, z, 16);
    z += __shfl_xor_sync(0xffffffffu, z, 8);
    z += __shfl_xor_sync(0xffffffffu, z, 4);
    z += __shfl_xor_sync(0xffffffffu, z, 2);
    z += __shfl_xor_sync(0xffffffffu, z, 1);
    const float inv = 1.f / z;
    const float p0 = e0 * inv;
    const float p1 = e1 * inv;

    float2 acc = {0.f, 0.f};
    for (int o = 0; o < NOFF; o++) {
        const int j = n - c_off[o];
        if (j < 0) break;
        const float w = __shfl_sync(0xffffffffu, (o < 32) ? p0 : p1, o & 31);
        const float* vrow = qkv + (size_t)j * (3 * DIM_D) + 2 * DIM_D + h * HDIM;
        float2 vv = *(const float2*)(vrow + d0);
        acc.x = fmaf(w, vv.x, acc.x);
        acc.y = fmaf(w, vv.y, acc.y);
    }

    const float g = if_gain[h];
    float* aout = (float*)g_aout;
    float2 outv = {acc.x * g, acc.y * g};
    *(float2*)(aout + (size_t)n * DIM_D + h * HDIM + d0) = outv;
}

// ---------------------------------------------------------------------------
extern "C" void kernel_launch(void* const* d_in, const int* in_sizes, int n_in,
                              void* d_out, int out_size)
{
    const float* x        = (const float*)d_in[0];
    const float* W_qkv    = (const float*)d_in[1];
    const float* b_qkv    = (const float*)d_in[2];
    const float* W_out    = (const float*)d_in[3];
    const float* b_out    = (const float*)d_in[4];
    const float* W_gate   = (const float*)d_in[5];
    const float* b_gate   = (const float*)d_in[6];
    const float* pos_bias = (const float*)d_in[7];
    const float* scale_e  = (const float*)d_in[8];
    const float* if_gain  = (const float*)d_in[9];
    const float* disp_amp = (const float*)d_in[10];
    float* out = (float*)d_out;

    cvt_all_kernel<<<2304, 256>>>(x, W_qkv, W_gate, W_out);

    {
        dim3 grid((3 * DIM_D) / GBN, SEQ_N / GBM);   // 24 x 32 = 768
        gemm_qkv_kernel<<<grid, 128>>>(b_qkv);
    }
    {
        dim3 grid(SEQ_N / 8, NHEAD);
        attn_kernel<<<grid, 256>>>(pos_bias, scale_e, if_gain, disp_amp);
    }
    {
        dim3 grid(DIM_D / GBN, SEQ_N / GBM);         // 8 x 32 = 256
        gemm_gate_kernel<<<grid, 128>>>(b_gate);
    }
    {
        dim3 grid(DIM_D / GBN, SEQ_N / GBM);
        gemm_out_kernel<<<grid, 128>>>(b_out, out);
    }
}

// round 7
// speedup vs baseline: 1.8450x; 1.0494x over previous
#include <cuda_runtime.h>
#include <cuda_bf16.h>
#include <math.h>
#include <stdint.h>

#define SEQ_N 2048
#define DIM_D 512
#define NHEAD 8
#define HDIM 64
#define NOFF 47
#define N1 2048          // fused GEMM1 output width (1536 qkv + 512 gate)

__constant__ int c_off[NOFF] = {
    0,1,2,3,4,5,6,7,8,9,10,11,12,13,14,15,16,17,18,19,20,21,22,23,24,25,26,
    27,28,29,30,31,32,48,64,96,128,192,256,384,512,768,1024,1536,2048,3072,4096
};

// Scratch
__device__ float g_qkv [SEQ_N * 3 * DIM_D];                      // 12 MB
__device__ float g_gsig[SEQ_N * DIM_D];                          // 4 MB sigmoid(x@Wg+b)
__device__ __align__(16) __nv_bfloat16 g_xhi [SEQ_N * DIM_D];
__device__ __align__(16) __nv_bfloat16 g_xlo [SEQ_N * DIM_D];
__device__ __align__(16) __nv_bfloat16 g_ghi [SEQ_N * DIM_D];    // gated activations
__device__ __align__(16) __nv_bfloat16 g_glo [SEQ_N * DIM_D];
__device__ __align__(16) __nv_bfloat16 g_w1hi[DIM_D * N1];       // [Wqkv | Wgate]
__device__ __align__(16) __nv_bfloat16 g_w1lo[DIM_D * N1];
__device__ __align__(16) __nv_bfloat16 g_wohi[DIM_D * DIM_D];
__device__ __align__(16) __nv_bfloat16 g_wolo[DIM_D * DIM_D];

// ---------------------------------------------------------------------------
// Fused fp32 -> bf16 hi/lo split.
// float4 regions: x 262144 | W1(merged qkv+gate) 262144 | wo 65536
// ---------------------------------------------------------------------------
__device__ __forceinline__ void cvt_store(float4 v, __nv_bfloat16* hi,
                                          __nv_bfloat16* lo, int i)
{
    __nv_bfloat16 h0 = __float2bfloat16(v.x);
    __nv_bfloat16 h1 = __float2bfloat16(v.y);
    __nv_bfloat16 h2 = __float2bfloat16(v.z);
    __nv_bfloat16 h3 = __float2bfloat16(v.w);
    __nv_bfloat162 hh0 = {h0, h1}, hh1 = {h2, h3};
    ((__nv_bfloat162*)hi)[i * 2 + 0] = hh0;
    ((__nv_bfloat162*)hi)[i * 2 + 1] = hh1;
    __nv_bfloat162 ll0 = {__float2bfloat16(v.x - __bfloat162float(h0)),
                          __float2bfloat16(v.y - __bfloat162float(h1))};
    __nv_bfloat162 ll1 = {__float2bfloat16(v.z - __bfloat162float(h2)),
                          __float2bfloat16(v.w - __bfloat162float(h3))};
    ((__nv_bfloat162*)lo)[i * 2 + 0] = ll0;
    ((__nv_bfloat162*)lo)[i * 2 + 1] = ll1;
}

__global__ void __launch_bounds__(256) cvt_all_kernel(
    const float* __restrict__ x, const float* __restrict__ wqkv,
    const float* __restrict__ wg, const float* __restrict__ wo)
{
    const int i = blockIdx.x * 256 + threadIdx.x;
    if (i < 262144) {
        cvt_store(((const float4*)x)[i], g_xhi, g_xlo, i);
    } else if (i < 524288) {
        const int j = i - 262144;           // W1 float4 index: row k, 512 f4/row
        const int k = j >> 9;
        const int cc = j & 511;             // float4 col
        float4 v = (cc < 384) ? ((const float4*)wqkv)[k * 384 + cc]
                              : ((const float4*)wg)[k * 128 + (cc - 384)];
        cvt_store(v, g_w1hi, g_w1lo, j);
    } else if (i < 589824) {
        const int j = i - 524288;
        cvt_store(((const float4*)wo)[j], g_wohi, g_wolo, j);
    }
}

// ---------------------------------------------------------------------------
// bf16 split MMA GEMM: 64x64 tile, GBK=32, 256 threads (8 warps 4x2,
// warp tile 16x32), 2-stage cp.async double buffer.
// EPI 1: fused qkv+gate epilogue. EPI 0: plain fp32 +bias.
// ---------------------------------------------------------------------------
#define GBM 64
#define GBN 64
#define GBK 32
#define ASTR 40
#define BSTR 72

__device__ __forceinline__ uint32_t smem_u32(const void* p)
{
    return (uint32_t)__cvta_generic_to_shared(p);
}

__device__ __forceinline__ void cp16(void* dst, const void* src)
{
    asm volatile("cp.async.cg.shared.global [%0], [%1], 16;\n"
                 :: "r"(smem_u32(dst)), "l"(src));
}

__device__ __forceinline__ void ldsm_x4(uint32_t& r0, uint32_t& r1,
                                        uint32_t& r2, uint32_t& r3, uint32_t addr)
{
    asm volatile("ldmatrix.sync.aligned.m8n8.x4.shared.b16 {%0,%1,%2,%3},[%4];"
                 : "=r"(r0), "=r"(r1), "=r"(r2), "=r"(r3) : "r"(addr));
}

__device__ __forceinline__ void ldsm_x4_t(uint32_t& r0, uint32_t& r1,
                                          uint32_t& r2, uint32_t& r3, uint32_t addr)
{
    asm volatile("ldmatrix.sync.aligned.m8n8.x4.trans.shared.b16 {%0,%1,%2,%3},[%4];"
                 : "=r"(r0), "=r"(r1), "=r"(r2), "=r"(r3) : "r"(addr));
}

__device__ __forceinline__ void mma_bf16(float* c, const uint32_t* a, const uint32_t* b)
{
    asm volatile(
        "mma.sync.aligned.m16n8k16.row.col.f32.bf16.bf16.f32 "
        "{%0,%1,%2,%3},{%4,%5,%6,%7},{%8,%9},{%0,%1,%2,%3};"
        : "+f"(c[0]), "+f"(c[1]), "+f"(c[2]), "+f"(c[3])
        : "r"(a[0]), "r"(a[1]), "r"(a[2]), "r"(a[3]), "r"(b[0]), "r"(b[1]));
}

template<int EPI>
__device__ __forceinline__ void mma_gemm_body(
    const __nv_bfloat16* __restrict__ Ahi, const __nv_bfloat16* __restrict__ Alo,
    const __nv_bfloat16* __restrict__ Bhi, const __nv_bfloat16* __restrict__ Blo,
    const float* __restrict__ bias1, const float* __restrict__ bias2,
    float* __restrict__ C, int N, int K)
{
    __shared__ __nv_bfloat16 sA[2][2][GBM][ASTR];
    __shared__ __nv_bfloat16 sB[2][2][GBK][BSTR];

    const int tid  = threadIdx.x;
    const int lane = tid & 31;
    const int warp = tid >> 5;
    const int wm = warp >> 1, wn = warp & 1;     // 4 x 2
    const int brow = blockIdx.y * GBM;
    const int bcol = blockIdx.x * GBN;

    float acc[4][4];
    #pragma unroll
    for (int j = 0; j < 4; j++)
        #pragma unroll
        for (int t = 0; t < 4; t++) acc[j][t] = 0.f;

    auto load_stage = [&](int stage, int k0) {
        #pragma unroll
        for (int i = 0; i < 2; i++) {            // A: 512 chunks, 2/thread
            const int c   = tid + i * 256;
            const int mat = c >> 8;
            const int rem = c & 255;
            const int row = rem >> 2;
            const int kc  = (rem & 3) * 8;
            const __nv_bfloat16* src = (mat ? Alo : Ahi) + (size_t)(brow + row) * K + k0 + kc;
            cp16(&sA[stage][mat][row][kc], src);
        }
        #pragma unroll
        for (int i = 0; i < 2; i++) {            // B: 512 chunks, 2/thread
            const int c   = tid + i * 256;
            const int mat = c >> 8;
            const int rem = c & 255;
            const int row = rem >> 3;
            const int col = (rem & 7) * 8;
            const __nv_bfloat16* src = (mat ? Blo : Bhi) + (size_t)(k0 + row) * N + bcol + col;
            cp16(&sB[stage][mat][row][col], src);
        }
        asm volatile("cp.async.commit_group;\n" ::);
    };

    load_stage(0, 0);
    int stage = 0;
    for (int k0 = 0; k0 < K; k0 += GBK) {
        if (k0 + GBK < K) {
            load_stage(stage ^ 1, k0 + GBK);
            asm volatile("cp.async.wait_group 1;\n" ::);
        } else {
            asm volatile("cp.async.wait_group 0;\n" ::);
        }
        __syncthreads();

        #pragma unroll
        for (int kk = 0; kk < GBK; kk += 16) {
            uint32_t ahi[4], alo[4], bhi[4][2], blo[4][2];
            const int row = wm * 16 + (lane & 15);
            const int kof = kk + (lane >> 4) * 8;
            ldsm_x4(ahi[0], ahi[1], ahi[2], ahi[3], smem_u32(&sA[stage][0][row][kof]));
            ldsm_x4(alo[0], alo[1], alo[2], alo[3], smem_u32(&sA[stage][1][row][kof]));
            #pragma unroll
            for (int np = 0; np < 2; np++) {
                const int krow = kk + (lane & 15);
                const int col  = wn * 32 + np * 16 + (lane >> 4) * 8;
                ldsm_x4_t(bhi[np*2][0], bhi[np*2][1], bhi[np*2+1][0], bhi[np*2+1][1],
                          smem_u32(&sB[stage][0][krow][col]));
                ldsm_x4_t(blo[np*2][0], blo[np*2][1], blo[np*2+1][0], blo[np*2+1][1],
                          smem_u32(&sB[stage][1][krow][col]));
            }
            #pragma unroll
            for (int nt = 0; nt < 4; nt++) {
                mma_bf16(acc[nt], ahi, bhi[nt]);
                mma_bf16(acc[nt], ahi, blo[nt]);
                mma_bf16(acc[nt], alo, bhi[nt]);
            }
        }
        __syncthreads();
        stage ^= 1;
    }

    // epilogue: warp tile rows [wm*16, +16), cols [wn*32, +32)
    const int gid = lane >> 2, tig = lane & 3;
    #pragma unroll
    for (int nt = 0; nt < 4; nt++) {
        const int row = brow + wm * 16 + gid;
        const int col = bcol + wn * 32 + nt * 8 + tig * 2;
        if (EPI == 0) {
            const float b0 = bias1[col], b1 = bias1[col + 1];
            float2 r0 = {acc[nt][0] + b0, acc[nt][1] + b1};
            float2 r1 = {acc[nt][2] + b0, acc[nt][3] + b1};
            *(float2*)(C + (size_t)row * N + col)       = r0;
            *(float2*)(C + (size_t)(row + 8) * N + col) = r1;
        } else {
            if (bcol < 3 * DIM_D) {   // qkv region (block-uniform)
                const float b0 = bias1[col], b1 = bias1[col + 1];
                float2 r0 = {acc[nt][0] + b0, acc[nt][1] + b1};
                float2 r1 = {acc[nt][2] + b0, acc[nt][3] + b1};
                float* q = (float*)g_qkv;
                *(float2*)(q + (size_t)row * (3 * DIM_D) + col)       = r0;
                *(float2*)(q + (size_t)(row + 8) * (3 * DIM_D) + col) = r1;
            } else {                  // gate region -> sigmoid
                const int gc = col - 3 * DIM_D;
                const float b0 = bias2[gc], b1 = bias2[gc + 1];
                float2 r0, r1;
                r0.x = 1.f / (1.f + __expf(-(acc[nt][0] + b0)));
                r0.y = 1.f / (1.f + __expf(-(acc[nt][1] + b1)));
                r1.x = 1.f / (1.f + __expf(-(acc[nt][2] + b0)));
                r1.y = 1.f / (1.f + __expf(-(acc[nt][3] + b1)));
                float* gs = (float*)g_gsig;
                *(float2*)(gs + (size_t)row * DIM_D + gc)       = r0;
                *(float2*)(gs + (size_t)(row + 8) * DIM_D + gc) = r1;
            }
        }
    }
}

__global__ void __launch_bounds__(256) gemm1_kernel(
    const float* __restrict__ b_qkv, const float* __restrict__ b_gate)
{
    mma_gemm_body<1>(g_xhi, g_xlo, g_w1hi, g_w1lo, b_qkv, b_gate,
                     nullptr, N1, DIM_D);
}

__global__ void __launch_bounds__(256) gemm2_kernel(
    const float* __restrict__ b_out, float* __restrict__ out)
{
    mma_gemm_body<0>(g_ghi, g_glo, g_wohi, g_wolo, b_out, nullptr,
                     out, DIM_D, DIM_D);
}

// ---------------------------------------------------------------------------
// Attention + gating: one warp per (n, h). Reads g_qkv, g_gsig; writes
// gated bf16 hi/lo to g_ghi/g_glo.
// ---------------------------------------------------------------------------
__global__ void __launch_bounds__(256) attn_kernel(
    const float* __restrict__ pos_bias,
    const float* __restrict__ scale_embed,
    const float* __restrict__ if_gain,
    const float* __restrict__ disp_amp)
{
    const float* qkv = (const float*)g_qkv;
    const int warp = threadIdx.x >> 5;
    const int lane = threadIdx.x & 31;
    const int n = blockIdx.x * 8 + warp;
    const int h = blockIdx.y;
    const int d0 = lane * 2;

    const float* qrow = qkv + (size_t)n * (3 * DIM_D) + h * HDIM;
    float2 q = *(const float2*)(qrow + d0);
    q.x *= 0.125f;
    q.y *= 0.125f;

    const float LM    = logf(4097.0f);
    const float wbase = 3.14159265358979f / LM;
    const float om = (h < 2) ? 0.f : (h < 4) ? wbase : (h < 6) ? 4.f * wbase : 6.f * wbase;
    const float da = disp_amp[h];

    float eb0, eb1 = 0.f;
    {
        const int o = lane;
        float ck = (om > 0.f) ? cosf(om * logf(1.f + (float)c_off[o])) : 0.f;
        eb0 = pos_bias[o * NHEAD + h] + ck * da;
        const int o2 = lane + 32;
        if (o2 < NOFF) {
            float ck2 = (om > 0.f) ? cosf(om * logf(1.f + (float)c_off[o2])) : 0.f;
            eb1 = pos_bias[o2 * NHEAD + h] + ck2 * da;
        }
    }

    float s0 = -INFINITY, s1 = -INFINITY;

    for (int o = 0; o < NOFF; o++) {
        const int j = n - c_off[o];
        if (j < 0) break;
        const float* krow = qkv + (size_t)j * (3 * DIM_D) + DIM_D + h * HDIM;
        float2 kv = *(const float2*)(krow + d0);
        float2 se = *(const float2*)(scale_embed + o * HDIM + d0);
        float p = q.x * kv.x * (1.f + se.x) + q.y * kv.y * (1.f + se.y);
        p += __shfl_xor_sync(0xffffffffu, p, 16);
        p += __shfl_xor_sync(0xffffffffu, p, 8);
        p += __shfl_xor_sync(0xffffffffu, p, 4);
        p += __shfl_xor_sync(0xffffffffu, p, 2);
        p += __shfl_xor_sync(0xffffffffu, p, 1);
        if (o < 32) { if (lane == o)      s0 = p + eb0; }
        else        { if (lane == o - 32) s1 = p + eb1; }
    }

    float m = fmaxf(s0, s1);
    m = fmaxf(m, __shfl_xor_sync(0xffffffffu, m, 16));
    m = fmaxf(m, __shfl_xor_sync(0xffffffffu, m, 8));
    m = fmaxf(m, __shfl_xor_sync(0xffffffffu, m, 4));
    m = fmaxf(m, __shfl_xor_sync(0xffffffffu, m, 2));
    m = fmaxf(m, __shfl_xor_sync(0xffffffffu, m, 1));

    float e0 = __expf(s0 - m);
    float e1 = __expf(s1 - m);
    float z = e0 + e1;
    z += __shfl_xor_sync(0xffffffffu, z, 16);
    z += __shfl_xor_sync(0xffffffffu, z, 8);
    z += __shfl_xor_sync(0xffffffffu, z, 4);
    z += __shfl_xor_sync(0xffffffffu, z, 2);
    z += __shfl_xor_sync(0xffffffffu, z, 1);
    const float inv = 1.f / z;
    const float p0 = e0 * inv;
    const float p1 = e1 * inv;

    float2 acc = {0.f, 0.f};
    for (int o = 0; o < NOFF; o++) {
        const int j = n - c_off[o];
        if (j < 0) break;
        const float w = __shfl_sync(0xffffffffu, (o < 32) ? p0 : p1, o & 31);
        const float* vrow = qkv + (size_t)j * (3 * DIM_D) + 2 * DIM_D + h * HDIM;
        float2 vv = *(const float2*)(vrow + d0);
        acc.x = fmaf(w, vv.x, acc.x);
        acc.y = fmaf(w, vv.y, acc.y);
    }

    const float g = if_gain[h];
    const size_t oidx = (size_t)n * DIM_D + h * HDIM + d0;
    float2 gs = *(const float2*)((const float*)g_gsig + oidx);
    float v0 = acc.x * g * gs.x;
    float v1 = acc.y * g * gs.y;

    __nv_bfloat16 h0 = __float2bfloat16(v0);
    __nv_bfloat16 h1 = __float2bfloat16(v1);
    __nv_bfloat162 hv = {h0, h1};
    __nv_bfloat162 lv = {__float2bfloat16(v0 - __bfloat162float(h0)),
                         __float2bfloat16(v1 - __bfloat162float(h1))};
    *(__nv_bfloat162*)((__nv_bfloat16*)g_ghi + oidx) = hv;
    *(__nv_bfloat162*)((__nv_bfloat16*)g_glo + oidx) = lv;
}

// ---------------------------------------------------------------------------
extern "C" void kernel_launch(void* const* d_in, const int* in_sizes, int n_in,
                              void* d_out, int out_size)
{
    const float* x        = (const float*)d_in[0];
    const float* W_qkv    = (const float*)d_in[1];
    const float* b_qkv    = (const float*)d_in[2];
    const float* W_out    = (const float*)d_in[3];
    const float* b_out    = (const float*)d_in[4];
    const float* W_gate   = (const float*)d_in[5];
    const float* b_gate   = (const float*)d_in[6];
    const float* pos_bias = (const float*)d_in[7];
    const float* scale_e  = (const float*)d_in[8];
    const float* if_gain  = (const float*)d_in[9];
    const float* disp_amp = (const float*)d_in[10];
    float* out = (float*)d_out;

    cvt_all_kernel<<<2304, 256>>>(x, W_qkv, W_gate, W_out);

    {
        dim3 grid(N1 / GBN, SEQ_N / GBM);            // 32 x 32 = 1024
        gemm1_kernel<<<grid, 256>>>(b_qkv, b_gate);
    }
    {
        dim3 grid(SEQ_N / 8, NHEAD);
        attn_kernel<<<grid, 256>>>(pos_bias, scale_e, if_gain, disp_amp);
    }
    {
        dim3 grid(DIM_D / GBN, SEQ_N / GBM);         // 8 x 32 = 256
        gemm2_kernel<<<grid, 256>>>(b_out, out);
    }
}